// round 8
// baseline (speedup 1.0000x reference)
#include <cuda_runtime.h>

#define N_BANDS   224
#define DM        64
#define DS        16
#define MAXROWS   10      // grid = 3*148 = 444 -> 9..10 rows per block
#define NTHREADS  256
#define NGROUPS   4       // 256/64
#define CSTRIDE   68      // coef row stride (floats), conflict-free LDS.128
#define ASTRIDE   9       // decay row stride (ull)
#define LN_EPS    1e-5f

typedef unsigned long long ull;

__global__ __launch_bounds__(NTHREADS, 3) void spectral_fused_kernel(
    const float* __restrict__ x,      // (N, 224)
    const float* __restrict__ w_in,   // (64,)
    const float* __restrict__ b_in,   // (64,)
    const float* __restrict__ A_log,  // (64,16)
    const float* __restrict__ Wb,     // (64,16)
    const float* __restrict__ Wc,     // (64,16)
    const float* __restrict__ Dvec,   // (64,)
    const float* __restrict__ Wo,     // (64,64) row-major (out,in)
    const float* __restrict__ bo,     // (64,)
    const float* __restrict__ gamma,  // (64,)
    const float* __restrict__ beta,   // (64,)
    float* __restrict__ out,          // (N, 64)
    int n_total)
{
    // every float4/ull-accessed array explicitly 16B-aligned; sh_x padded to
    // a multiple of 4 floats so layout stays 16B-clean regardless of order
    __shared__ alignas(16) float sh_x[MAXROWS * N_BANDS + 4];
    __shared__ alignas(16) float sh_coef[DM * CSTRIDE];
    __shared__ alignas(16) ull   sh_ap[DM * ASTRIDE];
    __shared__ alignas(16) float sh_out[MAXROWS][DM];
    __shared__ alignas(16) float sh_proj[4][DS];
    __shared__ float sh_k0w[DM], sh_k0b[DM];
    __shared__ unsigned sh_emin[NTHREADS / 32];
    __shared__ alignas(16) float2 sh_part[MAXROWS][2];

    const int tid = threadIdx.x;
    const int d   = tid & (DM - 1);
    const int nl  = tid >> 6;

    // balanced row partition over gridDim.x blocks
    const int row0  = (int)(((long long)blockIdx.x * n_total) / gridDim.x);
    const int row1  = (int)(((long long)(blockIdx.x + 1) * n_total) / gridDim.x);
    const int nrows = row1 - row0;

    const float bod = bo[d], gd = gamma[d], btd = beta[d];

    // ---- phase 1a: stage x tile (coalesced float4) ----
    {
        const float4* xsrc = reinterpret_cast<const float4*>(x + (size_t)row0 * N_BANDS);
        float4* xdst = reinterpret_cast<float4*>(sh_x);
        const int nvec = nrows * (N_BANDS / 4);
        for (int i = tid; i < nvec; i += NTHREADS) xdst[i] = xsrc[i];
    }
    // ---- phase 1b: projections wb = w_in^T Wb etc. (64 pairs x 4 pieces) ----
    {
        const int pair = tid >> 2, piece = tid & 3;
        const int s = pair & (DS - 1), which = pair >> 4;
        const float* W = (which < 2) ? Wb : Wc;
        const float* v = (which & 1) ? b_in : w_in;
        const int dd0 = piece * 16;
        float acc = 0.f;
        #pragma unroll 16
        for (int j = 0; j < 16; ++j) acc += v[dd0 + j] * W[(dd0 + j) * DS + s];
        acc += __shfl_xor_sync(0xffffffffu, acc, 1);
        acc += __shfl_xor_sync(0xffffffffu, acc, 2);
        if (piece == 0) sh_proj[which][s] = acc;
    }
    __syncthreads();

    // ---- phase 2: decays + coefficient algebra (thread: d2 = tid/4, 4 s-values) ----
    {
        const int d2 = tid >> 2, s0 = (tid & 3) * 4;
        const float wd = w_in[d2], bd = b_in[d2];
        float emin = 1e30f, kw = 0.f, kb = 0.f;
        float a0 = 0.f, a1 = 0.f, a2v = 0.f, a3 = 0.f;
        #pragma unroll
        for (int j = 0; j < 4; ++j) {
            int s = s0 + j;
            float e = expf(A_log[d2 * DS + s]);
            emin = fminf(emin, e);
            float av = expf(-e);
            if (j == 0) a0 = av; else if (j == 1) a1 = av;
            else if (j == 2) a2v = av; else a3 = av;
            float S0 = (1.0f - __powf(av, (float)N_BANDS)) / (1.0f - av);
            float swb = sh_proj[0][s], sbb = sh_proj[1][s];
            float swc = sh_proj[2][s], sbc = sh_proj[3][s];
            float P2 = wd * swb;
            float P1 = wd * sbb + bd * swb;
            float P0 = bd * sbb * S0;
            sh_coef[d2 * CSTRIDE +      s] = P2 * swc;
            sh_coef[d2 * CSTRIDE + 16 + s] = P1 * swc;
            sh_coef[d2 * CSTRIDE + 32 + s] = P2 * sbc;
            sh_coef[d2 * CSTRIDE + 48 + s] = P1 * sbc;
            kw += P0 * swc;
            kb += P0 * sbc;
        }
        {
            float2 v0 = make_float2(a0, a1);
            float2 v1 = make_float2(a2v, a3);
            sh_ap[d2 * ASTRIDE + (s0 >> 1)]     = *reinterpret_cast<ull*>(&v0);
            sh_ap[d2 * ASTRIDE + (s0 >> 1) + 1] = *reinterpret_cast<ull*>(&v1);
        }
        kw += __shfl_xor_sync(0xffffffffu, kw, 1);
        kw += __shfl_xor_sync(0xffffffffu, kw, 2);
        kb += __shfl_xor_sync(0xffffffffu, kb, 1);
        kb += __shfl_xor_sync(0xffffffffu, kb, 2);
        if ((tid & 3) == 0) {
            sh_k0w[d2] = kw + Dvec[d2] * wd;
            sh_k0b[d2] = kb + Dvec[d2] * bd;
        }
        unsigned em = __reduce_min_sync(0xffffffffu, __float_as_uint(emin));
        if ((tid & 31) == 0) sh_emin[tid >> 5] = em;
    }
    __syncthreads();

    // ---- truncation cutoff ----
    // tail rel err <= exp(-10)/(1-a_max) ~ 9e-5 worst case; a->1 -> full loop
    int c0;
    {
        unsigned m = sh_emin[0];
        #pragma unroll
        for (int i = 1; i < NTHREADS / 32; ++i) m = min(m, sh_emin[i]);
        float e_min = __uint_as_float(m);
        int K = (int)ceilf(10.0f / e_min);
        K = (K + 1) & ~1;
        if (K > N_BANDS) K = N_BANDS;
        c0 = N_BANDS - K;
    }

    ull ap[DS / 2];
    #pragma unroll
    for (int i = 0; i < DS / 2; ++i) ap[i] = sh_ap[d * ASTRIDE + i];

    const float4* cf = reinterpret_cast<const float4*>(sh_coef + d * CSTRIDE);
    const float k0w = sh_k0w[d], k0b = sh_k0b[d];

    // ---- phase 3: per-row Horner scan with software-pipelined x loads ----
    #pragma unroll 1
    for (int row = nl; row < nrows; row += NGROUPS) {
        const float* xr = sh_x + row * N_BANDS;

        ull s1p[DS / 2], s2p[DS / 2];
        #pragma unroll
        for (int i = 0; i < DS / 2; ++i) { s1p[i] = 0ULL; s2p[i] = 0ULL; }

        float2 xv = *reinterpret_cast<const float2*>(xr + c0);
        #pragma unroll 2
        for (int c = c0; c < N_BANDS; c += 2) {
            float2 xn = *reinterpret_cast<const float2*>(xr + c + 2); // padded
            ull xp0, xp1, xx0, xx1;
            asm("mov.b64 %0, {%1, %1};" : "=l"(xp0) : "f"(xv.x));
            asm("mov.b64 %0, {%1, %1};" : "=l"(xp1) : "f"(xv.y));
            asm("mul.rn.f32x2 %0, %1, %2;" : "=l"(xx0) : "l"(xp0), "l"(xp0));
            asm("mul.rn.f32x2 %0, %1, %2;" : "=l"(xx1) : "l"(xp1), "l"(xp1));
            #pragma unroll
            for (int i = 0; i < DS / 2; ++i) {
                asm("fma.rn.f32x2 %0, %1, %2, %3;"
                    : "=l"(s1p[i]) : "l"(s1p[i]), "l"(ap[i]), "l"(xp0));
                asm("fma.rn.f32x2 %0, %1, %2, %3;"
                    : "=l"(s2p[i]) : "l"(s2p[i]), "l"(ap[i]), "l"(xx0));
            }
            #pragma unroll
            for (int i = 0; i < DS / 2; ++i) {
                asm("fma.rn.f32x2 %0, %1, %2, %3;"
                    : "=l"(s1p[i]) : "l"(s1p[i]), "l"(ap[i]), "l"(xp1));
                asm("fma.rn.f32x2 %0, %1, %2, %3;"
                    : "=l"(s2p[i]) : "l"(s2p[i]), "l"(ap[i]), "l"(xx1));
            }
            xv = xn;
        }

        float S1[DS], S2[DS];
        #pragma unroll
        for (int i = 0; i < DS / 2; ++i) {
            asm("mov.b64 {%0, %1}, %2;" : "=f"(S1[2*i]), "=f"(S1[2*i+1]) : "l"(s1p[i]));
            asm("mov.b64 {%0, %1}, %2;" : "=f"(S2[2*i]), "=f"(S2[2*i+1]) : "l"(s2p[i]));
        }

        float accw = 0.f, accb = 0.f;
        #pragma unroll
        for (int i = 0; i < 4; ++i) {
            float4 t = cf[i];
            accw += t.x * S2[4*i] + t.y * S2[4*i+1] + t.z * S2[4*i+2] + t.w * S2[4*i+3];
        }
        #pragma unroll
        for (int i = 0; i < 4; ++i) {
            float4 t = cf[4 + i];
            accw += t.x * S1[4*i] + t.y * S1[4*i+1] + t.z * S1[4*i+2] + t.w * S1[4*i+3];
        }
        #pragma unroll
        for (int i = 0; i < 4; ++i) {
            float4 t = cf[8 + i];
            accb += t.x * S2[4*i] + t.y * S2[4*i+1] + t.z * S2[4*i+2] + t.w * S2[4*i+3];
        }
        #pragma unroll
        for (int i = 0; i < 4; ++i) {
            float4 t = cf[12 + i];
            accb += t.x * S1[4*i] + t.y * S1[4*i+1] + t.z * S1[4*i+2] + t.w * S1[4*i+3];
        }
        const float xlast = xr[N_BANDS - 1];
        sh_out[row][d] = xlast * (accw + k0w) + (accb + k0b);
    }
    __syncthreads();

    // ---- phase 4: out-proj + layernorm partials ----
    const float4* wrow = reinterpret_cast<const float4*>(Wo + d * DM);
    float zbuf[(MAXROWS + NGROUPS - 1) / NGROUPS];   // <= 3
    #pragma unroll 1
    for (int row = nl, j = 0; row < nrows; row += NGROUPS, ++j) {
        const float4* orow = reinterpret_cast<const float4*>(&sh_out[row][0]);
        float zz = bod;
        #pragma unroll
        for (int i = 0; i < DM / 4; ++i) {
            float4 w = wrow[i];
            float4 o4 = orow[i];
            zz += o4.x * w.x + o4.y * w.y + o4.z * w.z + o4.w * w.w;
        }
        zbuf[j] = zz;
        float sum = zz, sq = zz * zz;
        #pragma unroll
        for (int off = 16; off > 0; off >>= 1) {
            sum += __shfl_xor_sync(0xffffffffu, sum, off);
            sq  += __shfl_xor_sync(0xffffffffu, sq,  off);
        }
        if ((tid & 31) == 0) sh_part[row][(tid >> 5) & 1] = make_float2(sum, sq);
    }
    __syncthreads();

    #pragma unroll 1
    for (int row = nl, j = 0; row < nrows; row += NGROUPS, ++j) {
        float2 p0 = sh_part[row][0], p1 = sh_part[row][1];
        float mu  = (p0.x + p1.x) * (1.0f / DM);
        float var = (p0.y + p1.y) * (1.0f / DM) - mu * mu;
        float rn = rsqrtf(var + LN_EPS);
        out[(size_t)(row0 + row) * DM + d] = gd * (zbuf[j] - mu) * rn + btd;
    }
}

extern "C" void kernel_launch(void* const* d_in, const int* in_sizes, int n_in,
                              void* d_out, int out_size) {
    const float* x     = (const float*)d_in[0];
    const float* w_in  = (const float*)d_in[1];
    const float* b_in  = (const float*)d_in[2];
    const float* A_log = (const float*)d_in[3];
    const float* Wb    = (const float*)d_in[4];
    const float* Wc    = (const float*)d_in[5];
    const float* Dv    = (const float*)d_in[6];
    const float* Wo    = (const float*)d_in[7];
    const float* bo    = (const float*)d_in[8];
    const float* gm    = (const float*)d_in[9];
    const float* bt    = (const float*)d_in[10];
    float* out = (float*)d_out;

    int N = in_sizes[0] / N_BANDS;          // 4096
    int grid = 3 * 148;                     // exactly 3 blocks per SM
    if ((N + grid - 1) / grid > MAXROWS) grid = (N + MAXROWS - 1) / MAXROWS;
    spectral_fused_kernel<<<grid, NTHREADS>>>(x, w_in, b_in, A_log, Wb, Wc, Dv,
                                              Wo, bo, gm, bt, out, N);
}

// round 9
// speedup vs baseline: 1.0022x; 1.0022x over previous
#include <cuda_runtime.h>

#define N_BANDS   224
#define DM        64
#define DS        16
#define MAXROWS   10      // grid = 3*148 = 444 -> 9..10 rows per block
#define NTHREADS  256
#define NGROUPS   4       // 256/64
#define CSTRIDE   68      // coef row stride (floats); 272B rows -> 16B aligned
#define ASTRIDE   9       // decay row stride (ull)
#define LN_EPS    1e-5f

typedef unsigned long long ull;

__global__ __launch_bounds__(NTHREADS, 3) void spectral_fused_kernel(
    const float* __restrict__ x,      // (N, 224)
    const float* __restrict__ w_in,   // (64,)
    const float* __restrict__ b_in,   // (64,)
    const float* __restrict__ A_log,  // (64,16)
    const float* __restrict__ Wb,     // (64,16)
    const float* __restrict__ Wc,     // (64,16)
    const float* __restrict__ Dvec,   // (64,)
    const float* __restrict__ Wo,     // (64,64) row-major (out,in)
    const float* __restrict__ bo,     // (64,)
    const float* __restrict__ gamma,  // (64,)
    const float* __restrict__ beta,   // (64,)
    float* __restrict__ out,          // (N, 64)
    int n_total)
{
    __shared__ alignas(16) float sh_x[MAXROWS * N_BANDS + 4];
    __shared__ alignas(16) float sh_coef[DM * CSTRIDE];
    __shared__ alignas(16) ull   sh_ap[DM * ASTRIDE];
    __shared__ alignas(16) float sh_out[MAXROWS][DM];
    __shared__ alignas(16) float sh_proj[4][DS];
    __shared__ float sh_k0w[DM], sh_k0b[DM];
    __shared__ unsigned sh_emin[NTHREADS / 32];
    __shared__ alignas(16) float2 sh_part[MAXROWS][2];

    const int tid = threadIdx.x;
    const int d   = tid & (DM - 1);
    const int nl  = tid >> 6;

    const int row0  = (int)(((long long)blockIdx.x * n_total) / gridDim.x);
    const int row1  = (int)(((long long)(blockIdx.x + 1) * n_total) / gridDim.x);
    const int nrows = row1 - row0;

    const float bod = bo[d], gd = gamma[d], btd = beta[d];

    // ---- phase 1a: stage x tile (coalesced float4) ----
    {
        const float4* xsrc = reinterpret_cast<const float4*>(x + (size_t)row0 * N_BANDS);
        float4* xdst = reinterpret_cast<float4*>(sh_x);
        const int nvec = nrows * (N_BANDS / 4);
        for (int i = tid; i < nvec; i += NTHREADS) xdst[i] = xsrc[i];
    }
    // ---- phase 1b: projections wb = w_in^T Wb etc. ----
    {
        const int pair = tid >> 2, piece = tid & 3;
        const int s = pair & (DS - 1), which = pair >> 4;
        const float* W = (which < 2) ? Wb : Wc;
        const float* v = (which & 1) ? b_in : w_in;
        const int dd0 = piece * 16;
        float acc = 0.f;
        #pragma unroll 16
        for (int j = 0; j < 16; ++j) acc += v[dd0 + j] * W[(dd0 + j) * DS + s];
        acc += __shfl_xor_sync(0xffffffffu, acc, 1);
        acc += __shfl_xor_sync(0xffffffffu, acc, 2);
        if (piece == 0) sh_proj[which][s] = acc;
    }
    __syncthreads();

    // ---- phase 2: decays + coefficient algebra ----
    {
        const int d2 = tid >> 2, s0 = (tid & 3) * 4;
        const float wd = w_in[d2], bd = b_in[d2];
        float emin = 1e30f, kw = 0.f, kb = 0.f;
        float a0 = 0.f, a1 = 0.f, a2v = 0.f, a3 = 0.f;
        #pragma unroll
        for (int j = 0; j < 4; ++j) {
            int s = s0 + j;
            float e = expf(A_log[d2 * DS + s]);
            emin = fminf(emin, e);
            float av = expf(-e);
            if (j == 0) a0 = av; else if (j == 1) a1 = av;
            else if (j == 2) a2v = av; else a3 = av;
            float S0 = (1.0f - __powf(av, (float)N_BANDS)) / (1.0f - av);
            float swb = sh_proj[0][s], sbb = sh_proj[1][s];
            float swc = sh_proj[2][s], sbc = sh_proj[3][s];
            float P2 = wd * swb;
            float P1 = wd * sbb + bd * swb;
            float P0 = bd * sbb * S0;
            sh_coef[d2 * CSTRIDE +      s] = P2 * swc;
            sh_coef[d2 * CSTRIDE + 16 + s] = P1 * swc;
            sh_coef[d2 * CSTRIDE + 32 + s] = P2 * sbc;
            sh_coef[d2 * CSTRIDE + 48 + s] = P1 * sbc;
            kw += P0 * swc;
            kb += P0 * sbc;
        }
        {
            float2 v0 = make_float2(a0, a1);
            float2 v1 = make_float2(a2v, a3);
            sh_ap[d2 * ASTRIDE + (s0 >> 1)]     = *reinterpret_cast<ull*>(&v0);
            sh_ap[d2 * ASTRIDE + (s0 >> 1) + 1] = *reinterpret_cast<ull*>(&v1);
        }
        kw += __shfl_xor_sync(0xffffffffu, kw, 1);
        kw += __shfl_xor_sync(0xffffffffu, kw, 2);
        kb += __shfl_xor_sync(0xffffffffu, kb, 1);
        kb += __shfl_xor_sync(0xffffffffu, kb, 2);
        if ((tid & 3) == 0) {
            sh_k0w[d2] = kw + Dvec[d2] * wd;
            sh_k0b[d2] = kb + Dvec[d2] * bd;
        }
        unsigned em = __reduce_min_sync(0xffffffffu, __float_as_uint(emin));
        if ((tid & 31) == 0) sh_emin[tid >> 5] = em;
    }
    __syncthreads();

    // ---- truncation cutoff ----
    // tail rel err <= exp(-10)/(1-a_max) ~ 9e-5 worst case; a->1 -> full loop
    int c0;
    {
        unsigned m = sh_emin[0];
        #pragma unroll
        for (int i = 1; i < NTHREADS / 32; ++i) m = min(m, sh_emin[i]);
        float e_min = __uint_as_float(m);
        int K = (int)ceilf(10.0f / e_min);
        K = (K + 1) & ~1;
        if (K > N_BANDS) K = N_BANDS;
        c0 = N_BANDS - K;
    }

    ull ap[DS / 2];
    #pragma unroll
    for (int i = 0; i < DS / 2; ++i) ap[i] = sh_ap[d * ASTRIDE + i];

    const ull* cfp = reinterpret_cast<const ull*>(sh_coef + d * CSTRIDE);
    const float k0w = sh_k0w[d], k0b = sh_k0b[d];

    // ---- phase 3: per-row Horner scan; epilogue stays fully packed ----
    #pragma unroll 1
    for (int row = nl; row < nrows; row += NGROUPS) {
        const float* xr = sh_x + row * N_BANDS;

        ull s1p[DS / 2], s2p[DS / 2];
        #pragma unroll
        for (int i = 0; i < DS / 2; ++i) { s1p[i] = 0ULL; s2p[i] = 0ULL; }

        float2 xv = *reinterpret_cast<const float2*>(xr + c0);
        #pragma unroll 2
        for (int c = c0; c < N_BANDS; c += 2) {
            float2 xn = *reinterpret_cast<const float2*>(xr + c + 2); // padded
            ull xp0, xp1, xx0, xx1;
            asm("mov.b64 %0, {%1, %1};" : "=l"(xp0) : "f"(xv.x));
            asm("mov.b64 %0, {%1, %1};" : "=l"(xp1) : "f"(xv.y));
            asm("mul.rn.f32x2 %0, %1, %2;" : "=l"(xx0) : "l"(xp0), "l"(xp0));
            asm("mul.rn.f32x2 %0, %1, %2;" : "=l"(xx1) : "l"(xp1), "l"(xp1));
            #pragma unroll
            for (int i = 0; i < DS / 2; ++i) {
                asm("fma.rn.f32x2 %0, %1, %2, %3;"
                    : "=l"(s1p[i]) : "l"(s1p[i]), "l"(ap[i]), "l"(xp0));
                asm("fma.rn.f32x2 %0, %1, %2, %3;"
                    : "=l"(s2p[i]) : "l"(s2p[i]), "l"(ap[i]), "l"(xx0));
            }
            #pragma unroll
            for (int i = 0; i < DS / 2; ++i) {
                asm("fma.rn.f32x2 %0, %1, %2, %3;"
                    : "=l"(s1p[i]) : "l"(s1p[i]), "l"(ap[i]), "l"(xp1));
                asm("fma.rn.f32x2 %0, %1, %2, %3;"
                    : "=l"(s2p[i]) : "l"(s2p[i]), "l"(ap[i]), "l"(xx1));
            }
            xv = xn;
        }

        // ---- packed epilogue: aw = sum c2w.s2 + c1w.s1 ; ab likewise ----
        ull aw = 0ULL, ab = 0ULL;
        #pragma unroll
        for (int i = 0; i < DS / 2; ++i) {
            ull c = cfp[i];                 // c2w pair
            asm("fma.rn.f32x2 %0, %1, %2, %3;" : "=l"(aw) : "l"(c), "l"(s2p[i]), "l"(aw));
        }
        #pragma unroll
        for (int i = 0; i < DS / 2; ++i) {
            ull c = cfp[8 + i];             // c1w pair
            asm("fma.rn.f32x2 %0, %1, %2, %3;" : "=l"(aw) : "l"(c), "l"(s1p[i]), "l"(aw));
        }
        #pragma unroll
        for (int i = 0; i < DS / 2; ++i) {
            ull c = cfp[16 + i];            // c2b pair
            asm("fma.rn.f32x2 %0, %1, %2, %3;" : "=l"(ab) : "l"(c), "l"(s2p[i]), "l"(ab));
        }
        #pragma unroll
        for (int i = 0; i < DS / 2; ++i) {
            ull c = cfp[24 + i];            // c1b pair
            asm("fma.rn.f32x2 %0, %1, %2, %3;" : "=l"(ab) : "l"(c), "l"(s1p[i]), "l"(ab));
        }
        float awl, awh, abl, abh;
        asm("mov.b64 {%0, %1}, %2;" : "=f"(awl), "=f"(awh) : "l"(aw));
        asm("mov.b64 {%0, %1}, %2;" : "=f"(abl), "=f"(abh) : "l"(ab));
        const float xlast = xr[N_BANDS - 1];
        sh_out[row][d] = xlast * ((awl + awh) + k0w) + ((abl + abh) + k0b);
    }
    __syncthreads();

    // ---- phase 4: out-proj + layernorm partials ----
    const float4* wrow = reinterpret_cast<const float4*>(Wo + d * DM);
    float zbuf[(MAXROWS + NGROUPS - 1) / NGROUPS];   // <= 3
    #pragma unroll 1
    for (int row = nl, j = 0; row < nrows; row += NGROUPS, ++j) {
        const float4* orow = reinterpret_cast<const float4*>(&sh_out[row][0]);
        float zz = bod;
        #pragma unroll
        for (int i = 0; i < DM / 4; ++i) {
            float4 w = wrow[i];
            float4 o4 = orow[i];
            zz += o4.x * w.x + o4.y * w.y + o4.z * w.z + o4.w * w.w;
        }
        zbuf[j] = zz;
        float sum = zz, sq = zz * zz;
        #pragma unroll
        for (int off = 16; off > 0; off >>= 1) {
            sum += __shfl_xor_sync(0xffffffffu, sum, off);
            sq  += __shfl_xor_sync(0xffffffffu, sq,  off);
        }
        if ((tid & 31) == 0) sh_part[row][(tid >> 5) & 1] = make_float2(sum, sq);
    }
    __syncthreads();

    #pragma unroll 1
    for (int row = nl, j = 0; row < nrows; row += NGROUPS, ++j) {
        float2 p0 = sh_part[row][0], p1 = sh_part[row][1];
        float mu  = (p0.x + p1.x) * (1.0f / DM);
        float var = (p0.y + p1.y) * (1.0f / DM) - mu * mu;
        float rn = rsqrtf(var + LN_EPS);
        out[(size_t)(row0 + row) * DM + d] = gd * (zbuf[j] - mu) * rn + btd;
    }
}

extern "C" void kernel_launch(void* const* d_in, const int* in_sizes, int n_in,
                              void* d_out, int out_size) {
    const float* x     = (const float*)d_in[0];
    const float* w_in  = (const float*)d_in[1];
    const float* b_in  = (const float*)d_in[2];
    const float* A_log = (const float*)d_in[3];
    const float* Wb    = (const float*)d_in[4];
    const float* Wc    = (const float*)d_in[5];
    const float* Dv    = (const float*)d_in[6];
    const float* Wo    = (const float*)d_in[7];
    const float* bo    = (const float*)d_in[8];
    const float* gm    = (const float*)d_in[9];
    const float* bt    = (const float*)d_in[10];
    float* out = (float*)d_out;

    int N = in_sizes[0] / N_BANDS;          // 4096
    int grid = 3 * 148;                     // 3 blocks per SM
    if ((N + grid - 1) / grid > MAXROWS) grid = (N + MAXROWS - 1) / MAXROWS;
    spectral_fused_kernel<<<grid, NTHREADS>>>(x, w_in, b_in, A_log, Wb, Wc, Dv,
                                              Wo, bo, gm, bt, out, N);
}

// round 10
// speedup vs baseline: 1.2581x; 1.2553x over previous
#include <cuda_runtime.h>

#define N_BANDS   224
#define DM        64
#define DS        16
#define MAXROWS   10      // grid = 3*148 = 444 -> 9..10 rows per block
#define NTHREADS  256
#define CSTRIDE   68      // coef row stride (floats); 272B rows, 16B aligned
#define ASTRIDE   9       // decay row stride (ull)
#define LN_EPS    1e-5f

typedef unsigned long long ull;

__global__ __launch_bounds__(NTHREADS, 3) void spectral_fused_kernel(
    const float* __restrict__ x,      // (N, 224)
    const float* __restrict__ w_in,   // (64,)
    const float* __restrict__ b_in,   // (64,)
    const float* __restrict__ A_log,  // (64,16)
    const float* __restrict__ Wb,     // (64,16)
    const float* __restrict__ Wc,     // (64,16)
    const float* __restrict__ Dvec,   // (64,)
    const float* __restrict__ Wo,     // (64,64) row-major (out,in)
    const float* __restrict__ bo,     // (64,)
    const float* __restrict__ gamma,  // (64,)
    const float* __restrict__ beta,   // (64,)
    float* __restrict__ out,          // (N, 64)
    int n_total)
{
    __shared__ alignas(16) float sh_x[MAXROWS * N_BANDS + 4];
    __shared__ alignas(16) float sh_coef[DM * CSTRIDE];
    __shared__ alignas(16) ull   sh_ap[DM * ASTRIDE];
    __shared__ alignas(16) float sh_out[MAXROWS][DM];
    __shared__ alignas(16) float sh_proj[4][DS];
    __shared__ float sh_k0w[DM], sh_k0b[DM];
    __shared__ unsigned sh_emin[NTHREADS / 32];
    __shared__ alignas(16) float2 sh_part[MAXROWS][4];

    const int tid  = threadIdx.x;
    const int t    = tid & 127;   // index within row-group
    const int g    = tid >> 7;    // row-group (2 groups of 128 threads)
    const int dd   = t >> 1;      // output channel
    const int half = t & 1;       // s-dimension half (8 states each)

    const int row0  = (int)(((long long)blockIdx.x * n_total) / gridDim.x);
    const int row1  = (int)(((long long)(blockIdx.x + 1) * n_total) / gridDim.x);
    const int nrows = row1 - row0;

    const float bod = bo[dd], gd = gamma[dd], btd = beta[dd];

    // ---- phase 1a: stage x tile (coalesced float4) ----
    {
        const float4* xsrc = reinterpret_cast<const float4*>(x + (size_t)row0 * N_BANDS);
        float4* xdst = reinterpret_cast<float4*>(sh_x);
        const int nvec = nrows * (N_BANDS / 4);
        for (int i = tid; i < nvec; i += NTHREADS) xdst[i] = xsrc[i];
    }
    // ---- phase 1b: projections wb = w_in^T Wb etc. ----
    {
        const int pair = tid >> 2, piece = tid & 3;
        const int s = pair & (DS - 1), which = pair >> 4;
        const float* W = (which < 2) ? Wb : Wc;
        const float* v = (which & 1) ? b_in : w_in;
        const int dd0 = piece * 16;
        float acc = 0.f;
        #pragma unroll 16
        for (int j = 0; j < 16; ++j) acc += v[dd0 + j] * W[(dd0 + j) * DS + s];
        acc += __shfl_xor_sync(0xffffffffu, acc, 1);
        acc += __shfl_xor_sync(0xffffffffu, acc, 2);
        if (piece == 0) sh_proj[which][s] = acc;
    }
    __syncthreads();

    // ---- phase 2: decays + coefficient algebra (thread: d2 = tid/4, 4 s) ----
    {
        const int d2 = tid >> 2, s0 = (tid & 3) * 4;
        const float wd = w_in[d2], bd = b_in[d2];
        float emin = 1e30f, kw = 0.f, kb = 0.f;
        float a0 = 0.f, a1 = 0.f, a2v = 0.f, a3 = 0.f;
        #pragma unroll
        for (int j = 0; j < 4; ++j) {
            int s = s0 + j;
            float e = expf(A_log[d2 * DS + s]);
            emin = fminf(emin, e);
            float av = expf(-e);
            if (j == 0) a0 = av; else if (j == 1) a1 = av;
            else if (j == 2) a2v = av; else a3 = av;
            float S0 = (1.0f - __powf(av, (float)N_BANDS)) / (1.0f - av);
            float swb = sh_proj[0][s], sbb = sh_proj[1][s];
            float swc = sh_proj[2][s], sbc = sh_proj[3][s];
            float P2 = wd * swb;
            float P1 = wd * sbb + bd * swb;
            float P0 = bd * sbb * S0;
            sh_coef[d2 * CSTRIDE +      s] = P2 * swc;
            sh_coef[d2 * CSTRIDE + 16 + s] = P1 * swc;
            sh_coef[d2 * CSTRIDE + 32 + s] = P2 * sbc;
            sh_coef[d2 * CSTRIDE + 48 + s] = P1 * sbc;
            kw += P0 * swc;
            kb += P0 * sbc;
        }
        {
            float2 v0 = make_float2(a0, a1);
            float2 v1 = make_float2(a2v, a3);
            sh_ap[d2 * ASTRIDE + (s0 >> 1)]     = *reinterpret_cast<ull*>(&v0);
            sh_ap[d2 * ASTRIDE + (s0 >> 1) + 1] = *reinterpret_cast<ull*>(&v1);
        }
        kw += __shfl_xor_sync(0xffffffffu, kw, 1);
        kw += __shfl_xor_sync(0xffffffffu, kw, 2);
        kb += __shfl_xor_sync(0xffffffffu, kb, 1);
        kb += __shfl_xor_sync(0xffffffffu, kb, 2);
        if ((tid & 3) == 0) {
            sh_k0w[d2] = kw + Dvec[d2] * wd;
            sh_k0b[d2] = kb + Dvec[d2] * bd;
        }
        unsigned em = __reduce_min_sync(0xffffffffu, __float_as_uint(emin));
        if ((tid & 31) == 0) sh_emin[tid >> 5] = em;
    }
    __syncthreads();

    // ---- truncation cutoff ----
    // tail rel err <= exp(-10)/(1-a_max) ~ 9e-5 worst case; a->1 -> full loop
    int c0;
    {
        unsigned m = sh_emin[0];
        #pragma unroll
        for (int i = 1; i < NTHREADS / 32; ++i) m = min(m, sh_emin[i]);
        float e_min = __uint_as_float(m);
        int K = (int)ceilf(10.0f / e_min);
        K = (K + 1) & ~1;
        if (K > N_BANDS) K = N_BANDS;
        c0 = N_BANDS - K;
    }

    // ---- per-thread decays: this half's 4 packed pairs ----
    ull ap2[4];
    #pragma unroll
    for (int i = 0; i < 4; ++i) ap2[i] = sh_ap[dd * ASTRIDE + half * 4 + i];

    const ull* cfp = reinterpret_cast<const ull*>(sh_coef + dd * CSTRIDE) + half * 4;
    const float k0w = sh_k0w[dd], k0b = sh_k0b[dd];

    // ---- phase 3: scan; 128 threads per row, half the s-state each ----
    #pragma unroll 1
    for (int row = g; row < nrows; row += 2) {
        const float* xr = sh_x + row * N_BANDS;

        ull s1p[4], s2p[4];
        #pragma unroll
        for (int i = 0; i < 4; ++i) { s1p[i] = 0ULL; s2p[i] = 0ULL; }

        float2 xv = *reinterpret_cast<const float2*>(xr + c0);
        #pragma unroll 2
        for (int c = c0; c < N_BANDS; c += 2) {
            float2 xn = *reinterpret_cast<const float2*>(xr + c + 2); // padded
            ull xp0, xp1, xx0, xx1;
            asm("mov.b64 %0, {%1, %1};" : "=l"(xp0) : "f"(xv.x));
            asm("mov.b64 %0, {%1, %1};" : "=l"(xp1) : "f"(xv.y));
            asm("mul.rn.f32x2 %0, %1, %2;" : "=l"(xx0) : "l"(xp0), "l"(xp0));
            asm("mul.rn.f32x2 %0, %1, %2;" : "=l"(xx1) : "l"(xp1), "l"(xp1));
            #pragma unroll
            for (int i = 0; i < 4; ++i) {
                asm("fma.rn.f32x2 %0, %1, %2, %3;"
                    : "=l"(s1p[i]) : "l"(s1p[i]), "l"(ap2[i]), "l"(xp0));
                asm("fma.rn.f32x2 %0, %1, %2, %3;"
                    : "=l"(s2p[i]) : "l"(s2p[i]), "l"(ap2[i]), "l"(xx0));
            }
            #pragma unroll
            for (int i = 0; i < 4; ++i) {
                asm("fma.rn.f32x2 %0, %1, %2, %3;"
                    : "=l"(s1p[i]) : "l"(s1p[i]), "l"(ap2[i]), "l"(xp1));
                asm("fma.rn.f32x2 %0, %1, %2, %3;"
                    : "=l"(s2p[i]) : "l"(s2p[i]), "l"(ap2[i]), "l"(xx1));
            }
            xv = xn;
        }

        // ---- packed epilogue over this half's 4 pairs ----
        ull aw = 0ULL, ab = 0ULL;
        #pragma unroll
        for (int i = 0; i < 4; ++i) {
            asm("fma.rn.f32x2 %0, %1, %2, %3;" : "=l"(aw) : "l"(cfp[i]),      "l"(s2p[i]), "l"(aw));
            asm("fma.rn.f32x2 %0, %1, %2, %3;" : "=l"(aw) : "l"(cfp[8 + i]),  "l"(s1p[i]), "l"(aw));
            asm("fma.rn.f32x2 %0, %1, %2, %3;" : "=l"(ab) : "l"(cfp[16 + i]), "l"(s2p[i]), "l"(ab));
            asm("fma.rn.f32x2 %0, %1, %2, %3;" : "=l"(ab) : "l"(cfp[24 + i]), "l"(s1p[i]), "l"(ab));
        }
        float awl, awh, abl, abh;
        asm("mov.b64 {%0, %1}, %2;" : "=f"(awl), "=f"(awh) : "l"(aw));
        asm("mov.b64 {%0, %1}, %2;" : "=f"(abl), "=f"(abh) : "l"(ab));
        float sw = awl + awh;
        float sb = abl + abh;
        // combine the two halves (adjacent lanes)
        sw += __shfl_xor_sync(0xffffffffu, sw, 1);
        sb += __shfl_xor_sync(0xffffffffu, sb, 1);
        const float xlast = xr[N_BANDS - 1];
        if (half == 0)
            sh_out[row][dd] = xlast * (sw + k0w) + (sb + k0b);
    }
    __syncthreads();

    // ---- phase 4: out-proj split across halves + layernorm ----
    const float4* wrow = reinterpret_cast<const float4*>(Wo + dd * DM + half * 32);
    float zbuf[(MAXROWS + 1) / 2];   // <= 5
    #pragma unroll 1
    for (int row = g, j = 0; row < nrows; row += 2, ++j) {
        const float4* orow = reinterpret_cast<const float4*>(&sh_out[row][0] + half * 32);
        float zz = 0.f;
        #pragma unroll
        for (int i = 0; i < 8; ++i) {
            float4 w = wrow[i];
            float4 o4 = orow[i];
            zz += o4.x * w.x + o4.y * w.y + o4.z * w.z + o4.w * w.w;
        }
        zz += __shfl_xor_sync(0xffffffffu, zz, 1);   // both halves -> full dot
        zz += bod;
        zbuf[j] = zz;
        float sum = zz, sq = zz * zz;
        #pragma unroll
        for (int off = 16; off > 0; off >>= 1) {
            sum += __shfl_xor_sync(0xffffffffu, sum, off);
            sq  += __shfl_xor_sync(0xffffffffu, sq,  off);
        }
        if ((t & 31) == 0) sh_part[row][t >> 5] = make_float2(sum, sq);
    }
    __syncthreads();

    #pragma unroll 1
    for (int row = g, j = 0; row < nrows; row += 2, ++j) {
        float2 p0 = sh_part[row][0], p1 = sh_part[row][1];
        float2 p2 = sh_part[row][2], p3 = sh_part[row][3];
        // each z counted twice (both halves) -> divide by 128
        float mu  = (p0.x + p1.x + p2.x + p3.x) * (1.0f / 128.0f);
        float var = (p0.y + p1.y + p2.y + p3.y) * (1.0f / 128.0f) - mu * mu;
        float rn = rsqrtf(var + LN_EPS);
        if (half == 0)
            out[(size_t)(row0 + row) * DM + dd] = gd * (zbuf[j] - mu) * rn + btd;
    }
}

extern "C" void kernel_launch(void* const* d_in, const int* in_sizes, int n_in,
                              void* d_out, int out_size) {
    const float* x     = (const float*)d_in[0];
    const float* w_in  = (const float*)d_in[1];
    const float* b_in  = (const float*)d_in[2];
    const float* A_log = (const float*)d_in[3];
    const float* Wb    = (const float*)d_in[4];
    const float* Wc    = (const float*)d_in[5];
    const float* Dv    = (const float*)d_in[6];
    const float* Wo    = (const float*)d_in[7];
    const float* bo    = (const float*)d_in[8];
    const float* gm    = (const float*)d_in[9];
    const float* bt    = (const float*)d_in[10];
    float* out = (float*)d_out;

    int N = in_sizes[0] / N_BANDS;          // 4096
    int grid = 3 * 148;                     // 3 blocks per SM
    if ((N + grid - 1) / grid > MAXROWS) grid = (N + MAXROWS - 1) / MAXROWS;
    spectral_fused_kernel<<<grid, NTHREADS>>>(x, w_in, b_in, A_log, Wb, Wc, Dv,
                                              Wo, bo, gm, bt, out, N);
}